// round 1
// baseline (speedup 1.0000x reference)
#include <cuda_runtime.h>
#include <cuda_bf16.h>
#include <cstdint>

// ---------------- problem constants ----------------
#define NB   32
#define NT   256
#define NC   384
#define NHD  6
#define HDD  64
#define NL   6
#define NH4  1536
#define NVOC 32000
#define NM   (NB*NT)          // 8192 tokens
#define EPS  1e-5f
#define ATT_SCALE 0.05103103630798288f   // 1/sqrt(384)  (source scales by n_embd!)

// ---------------- scratch (no allocation allowed) ----------------
__device__ float g_x  [NM*NC];
__device__ float g_h  [NM*NC];
__device__ float g_q  [NM*NC];
__device__ float g_k  [NM*NC];
__device__ float g_v  [NM*NC];
__device__ float g_att[NM*NC];
__device__ float g_ffn[NM*NH4];

// ---------------- embedding ----------------
__global__ void embed_kernel(const int* __restrict__ idx,
                             const float* __restrict__ tok,
                             const float* __restrict__ pos,
                             float* __restrict__ x)
{
    int i = blockIdx.x * blockDim.x + threadIdx.x;
    if (i >= NM * NC) return;
    int m = i / NC, c = i - m * NC;
    int t = m & (NT - 1);
    x[i] = tok[idx[m] * NC + c] + pos[t * NC + c];
}

// ---------------- layernorm: one block (128 thr) per row of 384 ----------------
__device__ __forceinline__ float blockSum128(float v, float* sm)
{
    int lane = threadIdx.x & 31, w = threadIdx.x >> 5;
    #pragma unroll
    for (int o = 16; o; o >>= 1) v += __shfl_xor_sync(0xffffffffu, v, o);
    if (lane == 0) sm[w] = v;
    __syncthreads();
    float r = sm[0] + sm[1] + sm[2] + sm[3];
    __syncthreads();
    return r;
}

__global__ void __launch_bounds__(128) ln_kernel(const float* __restrict__ x,
                                                 const float* __restrict__ g,
                                                 const float* __restrict__ b,
                                                 float* __restrict__ out)
{
    __shared__ float sm[4];
    int row = blockIdx.x;
    const float* xr = x + (size_t)row * NC;
    int tid = threadIdx.x;
    float v0 = xr[tid], v1 = xr[tid + 128], v2 = xr[tid + 256];
    float mean = blockSum128(v0 + v1 + v2, sm) * (1.0f / NC);
    float d0 = v0 - mean, d1 = v1 - mean, d2 = v2 - mean;
    float var = blockSum128(d0 * d0 + d1 * d1 + d2 * d2, sm) * (1.0f / NC);
    float inv = rsqrtf(var + EPS);
    float* orow = out + (size_t)row * NC;
    orow[tid      ] = d0 * inv * g[tid      ] + b[tid      ];
    orow[tid + 128] = d1 * inv * g[tid + 128] + b[tid + 128];
    orow[tid + 256] = d2 * inv * g[tid + 256] + b[tid + 256];
}

// ---------------- tiled SGEMM: C = A[MxK] * B[KxN] (+bias)(+res)(relu) ----------------
template<bool RELU, bool RESIDUAL>
__global__ void __launch_bounds__(256) sgemm_kernel(const float* __restrict__ A,
                                                    const float* __restrict__ B,
                                                    const float* __restrict__ bias,
                                                    const float* __restrict__ res,
                                                    float* __restrict__ C,
                                                    int M, int N, int K)
{
    constexpr int BM = 128, BN = 128, BK = 8, TM = 8, TN = 8;
    __shared__ float As[BK][BM];
    __shared__ float Bs[BK][BN];

    int tid  = threadIdx.x;
    int trow = tid >> 4;          // 0..15
    int tcol = tid & 15;          // 0..15

    int aRow = tid >> 1;          // 0..127
    int aCol = (tid & 1) * 4;     // 0 or 4
    int bRow = tid >> 5;          // 0..7
    int bCol = (tid & 31) * 4;    // 0..124

    const float* Ag = A + (size_t)(blockIdx.y * BM + aRow) * K + aCol;
    const float* Bg = B + (size_t)bRow * N + blockIdx.x * BN + bCol;

    float acc[TM][TN];
    #pragma unroll
    for (int i = 0; i < TM; i++)
        #pragma unroll
        for (int j = 0; j < TN; j++) acc[i][j] = 0.f;

    for (int k0 = 0; k0 < K; k0 += BK) {
        float4 a4 = *(const float4*)Ag;
        float4 b4 = *(const float4*)Bg;
        As[aCol + 0][aRow] = a4.x;
        As[aCol + 1][aRow] = a4.y;
        As[aCol + 2][aRow] = a4.z;
        As[aCol + 3][aRow] = a4.w;
        *(float4*)&Bs[bRow][bCol] = b4;
        __syncthreads();

        #pragma unroll
        for (int kk = 0; kk < BK; kk++) {
            float4 a0 = *(const float4*)&As[kk][trow * TM];
            float4 a1 = *(const float4*)&As[kk][trow * TM + 4];
            float4 c0 = *(const float4*)&Bs[kk][tcol * TN];
            float4 c1 = *(const float4*)&Bs[kk][tcol * TN + 4];
            float ar[TM] = {a0.x, a0.y, a0.z, a0.w, a1.x, a1.y, a1.z, a1.w};
            float br[TN] = {c0.x, c0.y, c0.z, c0.w, c1.x, c1.y, c1.z, c1.w};
            #pragma unroll
            for (int i = 0; i < TM; i++)
                #pragma unroll
                for (int j = 0; j < TN; j++)
                    acc[i][j] = fmaf(ar[i], br[j], acc[i][j]);
        }
        __syncthreads();
        Ag += BK;
        Bg += (size_t)BK * N;
    }

    int mBase = blockIdx.y * BM + trow * TM;
    int nBase = blockIdx.x * BN + tcol * TN;
    float4 bb0 = make_float4(0, 0, 0, 0), bb1 = make_float4(0, 0, 0, 0);
    if (bias) {
        bb0 = *(const float4*)&bias[nBase];
        bb1 = *(const float4*)&bias[nBase + 4];
    }
    #pragma unroll
    for (int i = 0; i < TM; i++) {
        size_t off = (size_t)(mBase + i) * N + nBase;
        float4 o0 = make_float4(acc[i][0] + bb0.x, acc[i][1] + bb0.y,
                                acc[i][2] + bb0.z, acc[i][3] + bb0.w);
        float4 o1 = make_float4(acc[i][4] + bb1.x, acc[i][5] + bb1.y,
                                acc[i][6] + bb1.z, acc[i][7] + bb1.w);
        if (RESIDUAL) {
            float4 r0 = *(const float4*)&res[off];
            float4 r1 = *(const float4*)&res[off + 4];
            o0.x += r0.x; o0.y += r0.y; o0.z += r0.z; o0.w += r0.w;
            o1.x += r1.x; o1.y += r1.y; o1.z += r1.z; o1.w += r1.w;
        }
        if (RELU) {
            o0.x = fmaxf(o0.x, 0.f); o0.y = fmaxf(o0.y, 0.f);
            o0.z = fmaxf(o0.z, 0.f); o0.w = fmaxf(o0.w, 0.f);
            o1.x = fmaxf(o1.x, 0.f); o1.y = fmaxf(o1.y, 0.f);
            o1.z = fmaxf(o1.z, 0.f); o1.w = fmaxf(o1.w, 0.f);
        }
        *(float4*)&C[off]     = o0;
        *(float4*)&C[off + 4] = o1;
    }
}

// ---------------- causal attention: one block (128 thr) per (b, h, t) ----------------
__global__ void __launch_bounds__(128) attn_kernel(const float* __restrict__ q,
                                                   const float* __restrict__ k,
                                                   const float* __restrict__ v,
                                                   float* __restrict__ out)
{
    __shared__ float qs[HDD];
    __shared__ float p[NT];
    __shared__ float smr[4];

    int t  = blockIdx.x;
    int bh = blockIdx.y;
    int b  = bh / NHD, h = bh - b * NHD;
    int tid = threadIdx.x;

    const float* qrow = q + (size_t)(b * NT + t) * NC + h * HDD;
    if (tid < HDD) qs[tid] = qrow[tid];
    __syncthreads();

    float lmax = -1e30f;
    for (int s = tid; s <= t; s += 128) {
        const float* krow = k + (size_t)(b * NT + s) * NC + h * HDD;
        float acc = 0.f;
        #pragma unroll
        for (int d = 0; d < HDD; d++) acc = fmaf(qs[d], krow[d], acc);
        acc *= ATT_SCALE;
        p[s] = acc;
        lmax = fmaxf(lmax, acc);
    }
    // block max
    {
        int lane = tid & 31, w = tid >> 5;
        #pragma unroll
        for (int o = 16; o; o >>= 1) lmax = fmaxf(lmax, __shfl_xor_sync(0xffffffffu, lmax, o));
        if (lane == 0) smr[w] = lmax;
        __syncthreads();
        lmax = fmaxf(fmaxf(smr[0], smr[1]), fmaxf(smr[2], smr[3]));
        __syncthreads();
    }
    float lsum = 0.f;
    for (int s = tid; s <= t; s += 128) {
        float e = __expf(p[s] - lmax);
        p[s] = e;
        lsum += e;
    }
    float Z = blockSum128(lsum, smr);   // includes syncthreads -> p visible
    float rZ = 1.0f / Z;

    if (tid < HDD) {
        const float* vcol = v + (size_t)b * NT * NC + h * HDD + tid;
        float acc = 0.f;
        for (int s = 0; s <= t; s++) acc = fmaf(p[s], vcol[(size_t)s * NC], acc);
        out[(size_t)(b * NT + t) * NC + h * HDD + tid] = acc * rZ;
    }
}

// ---------------- launch ----------------
static inline void gemm(const float* A, const float* B, const float* bias,
                        const float* res, float* C, int M, int N, int K,
                        bool relu, bool residual)
{
    dim3 grid(N / 128, M / 128);
    if (relu)          sgemm_kernel<true , false><<<grid, 256>>>(A, B, bias, res, C, M, N, K);
    else if (residual) sgemm_kernel<false, true ><<<grid, 256>>>(A, B, bias, res, C, M, N, K);
    else               sgemm_kernel<false, false><<<grid, 256>>>(A, B, bias, res, C, M, N, K);
}

extern "C" void kernel_launch(void* const* d_in, const int* in_sizes, int n_in,
                              void* d_out, int out_size)
{
    const int*   idx     = (const int*)  d_in[0];
    const float* tok_emb = (const float*)d_in[1];
    const float* pos_emb = (const float*)d_in[2];
    const float* ln1_g   = (const float*)d_in[3];
    const float* ln1_b   = (const float*)d_in[4];
    const float* wq      = (const float*)d_in[5];
    const float* wk      = (const float*)d_in[6];
    const float* wv      = (const float*)d_in[7];
    const float* wo      = (const float*)d_in[8];
    const float* wo_b    = (const float*)d_in[9];
    const float* ln2_g   = (const float*)d_in[10];
    const float* ln2_b   = (const float*)d_in[11];
    const float* w1      = (const float*)d_in[12];
    const float* b1      = (const float*)d_in[13];
    const float* w2      = (const float*)d_in[14];
    const float* b2      = (const float*)d_in[15];
    const float* lnf_g   = (const float*)d_in[16];
    const float* lnf_b   = (const float*)d_in[17];
    const float* lm_w    = (const float*)d_in[18];
    const float* lm_b    = (const float*)d_in[19];
    float* out = (float*)d_out;

    float *x, *h, *q, *k, *v, *att, *ffn;
    cudaGetSymbolAddress((void**)&x,   g_x);
    cudaGetSymbolAddress((void**)&h,   g_h);
    cudaGetSymbolAddress((void**)&q,   g_q);
    cudaGetSymbolAddress((void**)&k,   g_k);
    cudaGetSymbolAddress((void**)&v,   g_v);
    cudaGetSymbolAddress((void**)&att, g_att);
    cudaGetSymbolAddress((void**)&ffn, g_ffn);

    embed_kernel<<<(NM * NC + 255) / 256, 256>>>(idx, tok_emb, pos_emb, x);

    for (int l = 0; l < NL; l++) {
        const float* Wq = wq + (size_t)l * NC * NC;
        const float* Wk = wk + (size_t)l * NC * NC;
        const float* Wv = wv + (size_t)l * NC * NC;
        const float* Wo = wo + (size_t)l * NC * NC;
        const float* W1 = w1 + (size_t)l * NC * NH4;
        const float* W2 = w2 + (size_t)l * NH4 * NC;

        ln_kernel<<<NM, 128>>>(x, ln1_g + l * NC, ln1_b + l * NC, h);
        gemm(h, Wq, nullptr, nullptr, q, NM, NC, NC, false, false);
        gemm(h, Wk, nullptr, nullptr, k, NM, NC, NC, false, false);
        gemm(h, Wv, nullptr, nullptr, v, NM, NC, NC, false, false);

        attn_kernel<<<dim3(NT, NB * NHD), 128>>>(q, k, v, att);

        gemm(att, Wo, wo_b + l * NC, x, x, NM, NC, NC, false, true);

        ln_kernel<<<NM, 128>>>(x, ln2_g + l * NC, ln2_b + l * NC, h);
        gemm(h, W1, b1 + l * NH4, nullptr, ffn, NM, NH4, NC, true, false);
        gemm(ffn, W2, b2 + l * NC, x, x, NM, NC, NH4, false, true);
    }

    ln_kernel<<<NM, 128>>>(x, lnf_g, lnf_b, h);
    gemm(h, lm_w, lm_b, nullptr, out, NM, NVOC, NC, false, false);
}

// round 2
// speedup vs baseline: 3.3182x; 3.3182x over previous
#include <cuda_runtime.h>
#include <cuda_bf16.h>
#include <cstdint>

// ---------------- problem constants ----------------
#define NB   32
#define NT   256
#define NC   384
#define NHD  6
#define HDD  64
#define NL   6
#define NH4  1536
#define NVOC 32000
#define NM   (NB*NT)          // 8192 tokens
#define EPS  1e-5f
#define ATT_SCALE 0.05103103630798288f   // 1/sqrt(384)

// ---------------- scratch ----------------
__device__ float g_x  [NM*NC];
__device__ float g_h  [NM*NC];
__device__ float g_q  [NM*NC];
__device__ float g_k  [NM*NC];
__device__ float g_v  [NM*NC];
__device__ float g_att[NM*NC];
__device__ float g_ffn[NM*NH4];

// ---------------- embedding ----------------
__global__ void embed_kernel(const int* __restrict__ idx,
                             const float* __restrict__ tok,
                             const float* __restrict__ pos,
                             float* __restrict__ x)
{
    int i = blockIdx.x * blockDim.x + threadIdx.x;
    if (i >= NM * NC) return;
    int m = i / NC, c = i - m * NC;
    int t = m & (NT - 1);
    x[i] = tok[idx[m] * NC + c] + pos[t * NC + c];
}

// ---------------- reductions ----------------
__device__ __forceinline__ float blockSum128(float v, float* sm)
{
    int lane = threadIdx.x & 31, w = threadIdx.x >> 5;
    #pragma unroll
    for (int o = 16; o; o >>= 1) v += __shfl_xor_sync(0xffffffffu, v, o);
    if (lane == 0) sm[w] = v;
    __syncthreads();
    float r = sm[0] + sm[1] + sm[2] + sm[3];
    __syncthreads();
    return r;
}

// ---------------- layernorm ----------------
__global__ void __launch_bounds__(128) ln_kernel(const float* __restrict__ x,
                                                 const float* __restrict__ g,
                                                 const float* __restrict__ b,
                                                 float* __restrict__ out)
{
    __shared__ float sm[4];
    int row = blockIdx.x;
    const float* xr = x + (size_t)row * NC;
    int tid = threadIdx.x;
    float v0 = xr[tid], v1 = xr[tid + 128], v2 = xr[tid + 256];
    float mean = blockSum128(v0 + v1 + v2, sm) * (1.0f / NC);
    float d0 = v0 - mean, d1 = v1 - mean, d2 = v2 - mean;
    float var = blockSum128(d0 * d0 + d1 * d1 + d2 * d2, sm) * (1.0f / NC);
    float inv = rsqrtf(var + EPS);
    float* orow = out + (size_t)row * NC;
    orow[tid      ] = d0 * inv * g[tid      ] + b[tid      ];
    orow[tid + 128] = d1 * inv * g[tid + 128] + b[tid + 128];
    orow[tid + 256] = d2 * inv * g[tid + 256] + b[tid + 256];
}

// ---------------- TF32 tensor-core GEMM ----------------
// C[M,N] = A[M,K] @ B[K,N] (+bias)(+res)(relu). fp32 in/out, tf32 mma.
// Block tile 128x128, K-tile 32. 256 threads = 8 warps (4M x 2N), warp tile 32x64.

__device__ __forceinline__ uint32_t f2tf32(float x)
{
    uint32_t u;
    asm("cvt.rna.tf32.f32 %0, %1;" : "=r"(u) : "f"(x));
    return u;
}

#define SA 36    // As row stride (words): 128 rows x 36
#define SB 136   // Bs row stride (words): 32 rows x 136

template<bool RELU, bool RESIDUAL>
__global__ void __launch_bounds__(256) tgemm_kernel(const float* __restrict__ A,
                                                    const float* __restrict__ B,
                                                    const float* __restrict__ bias,
                                                    const float* __restrict__ res,
                                                    float* __restrict__ C,
                                                    int M, int N, int K)
{
    __shared__ uint32_t As[128 * SA];
    __shared__ uint32_t Bs[32 * SB];

    const int tid    = threadIdx.x;
    const int warpId = tid >> 5;
    const int lane   = tid & 31;
    const int group  = lane >> 2;   // 0..7
    const int tig    = lane & 3;    // 0..3
    const int warpM  = warpId >> 1; // 0..3 -> rows warpM*32
    const int warpN  = warpId & 1;  // 0..1 -> cols warpN*64

    const int blockM = blockIdx.y * 128;
    const int blockN = blockIdx.x * 128;

    // global load mapping (coalesced float4)
    const int aRow  = tid >> 3;          // 0..31? no: tid 0..255 >>3 -> 0..31 ... need 0..127
    // A: 128x32 floats = 1024 float4; idx = it*256 + tid, row = idx>>3, col4 = (idx&7)*4
    // B: 32x128 floats = 1024 float4; row = idx>>5, col4 = (idx&31)*4
    (void)aRow;

    float4 ra[4], rb[4];
    const float* Ap[4];
    const float* Bp[4];
    #pragma unroll
    for (int i = 0; i < 4; i++) {
        int idx = i * 256 + tid;
        int ar = idx >> 3, ac = (idx & 7) * 4;
        int br = idx >> 5, bc = (idx & 31) * 4;
        Ap[i] = A + (size_t)(blockM + ar) * K + ac;
        Bp[i] = B + (size_t)br * N + blockN + bc;
    }

    float c[2][8][4];
    #pragma unroll
    for (int mt = 0; mt < 2; mt++)
        #pragma unroll
        for (int nt = 0; nt < 8; nt++)
            #pragma unroll
            for (int r = 0; r < 4; r++) c[mt][nt][r] = 0.f;

    const int nk = K >> 5;

    // prologue: load + store tile 0
    #pragma unroll
    for (int i = 0; i < 4; i++) { ra[i] = *(const float4*)Ap[i]; rb[i] = *(const float4*)Bp[i]; }
    #pragma unroll
    for (int i = 0; i < 4; i++) {
        int idx = i * 256 + tid;
        int ar = idx >> 3, ac = (idx & 7) * 4;
        int br = idx >> 5, bc = (idx & 31) * 4;
        uint32_t* as = &As[ar * SA + ac];
        as[0] = f2tf32(ra[i].x); as[1] = f2tf32(ra[i].y);
        as[2] = f2tf32(ra[i].z); as[3] = f2tf32(ra[i].w);
        uint32_t* bs = &Bs[br * SB + bc];
        bs[0] = f2tf32(rb[i].x); bs[1] = f2tf32(rb[i].y);
        bs[2] = f2tf32(rb[i].z); bs[3] = f2tf32(rb[i].w);
    }
    __syncthreads();

    for (int kt = 0; kt < nk; kt++) {
        if (kt + 1 < nk) {
            #pragma unroll
            for (int i = 0; i < 4; i++) {
                Ap[i] += 32;
                Bp[i] += (size_t)32 * N;
                ra[i] = *(const float4*)Ap[i];
                rb[i] = *(const float4*)Bp[i];
            }
        }

        // compute on current smem tile
        #pragma unroll
        for (int kk = 0; kk < 4; kk++) {
            const int k = kk * 8;
            uint32_t af[2][4];
            #pragma unroll
            for (int mt = 0; mt < 2; mt++) {
                int mrow = warpM * 32 + mt * 16 + group;
                af[mt][0] = As[(mrow    ) * SA + k + tig    ];
                af[mt][1] = As[(mrow + 8) * SA + k + tig    ];
                af[mt][2] = As[(mrow    ) * SA + k + tig + 4];
                af[mt][3] = As[(mrow + 8) * SA + k + tig + 4];
            }
            uint32_t bf[8][2];
            #pragma unroll
            for (int nt = 0; nt < 8; nt++) {
                int ncol = warpN * 64 + nt * 8 + group;
                bf[nt][0] = Bs[(k + tig    ) * SB + ncol];
                bf[nt][1] = Bs[(k + tig + 4) * SB + ncol];
            }
            #pragma unroll
            for (int mt = 0; mt < 2; mt++)
                #pragma unroll
                for (int nt = 0; nt < 8; nt++) {
                    asm volatile(
                        "mma.sync.aligned.m16n8k8.row.col.f32.tf32.tf32.f32 "
                        "{%0,%1,%2,%3}, {%4,%5,%6,%7}, {%8,%9}, {%0,%1,%2,%3};"
                        : "+f"(c[mt][nt][0]), "+f"(c[mt][nt][1]),
                          "+f"(c[mt][nt][2]), "+f"(c[mt][nt][3])
                        : "r"(af[mt][0]), "r"(af[mt][1]), "r"(af[mt][2]), "r"(af[mt][3]),
                          "r"(bf[nt][0]), "r"(bf[nt][1]));
                }
        }
        __syncthreads();

        if (kt + 1 < nk) {
            #pragma unroll
            for (int i = 0; i < 4; i++) {
                int idx = i * 256 + tid;
                int ar = idx >> 3, ac = (idx & 7) * 4;
                int br = idx >> 5, bc = (idx & 31) * 4;
                uint32_t* as = &As[ar * SA + ac];
                as[0] = f2tf32(ra[i].x); as[1] = f2tf32(ra[i].y);
                as[2] = f2tf32(ra[i].z); as[3] = f2tf32(ra[i].w);
                uint32_t* bs = &Bs[br * SB + bc];
                bs[0] = f2tf32(rb[i].x); bs[1] = f2tf32(rb[i].y);
                bs[2] = f2tf32(rb[i].z); bs[3] = f2tf32(rb[i].w);
            }
            __syncthreads();
        }
    }

    // epilogue
    #pragma unroll
    for (int mt = 0; mt < 2; mt++) {
        int row0 = blockM + warpM * 32 + mt * 16 + group;
        #pragma unroll
        for (int nt = 0; nt < 8; nt++) {
            int col = blockN + warpN * 64 + nt * 8 + tig * 2;
            float b0 = 0.f, b1 = 0.f;
            if (bias) { b0 = bias[col]; b1 = bias[col + 1]; }
            // rows row0 and row0+8
            #pragma unroll
            for (int h = 0; h < 2; h++) {
                int row = row0 + h * 8;
                size_t off = (size_t)row * N + col;
                float o0 = c[mt][nt][h * 2 + 0] + b0;
                float o1 = c[mt][nt][h * 2 + 1] + b1;
                if (RESIDUAL) {
                    float2 r2 = *(const float2*)&res[off];
                    o0 += r2.x; o1 += r2.y;
                }
                if (RELU) { o0 = fmaxf(o0, 0.f); o1 = fmaxf(o1, 0.f); }
                *(float2*)&C[off] = make_float2(o0, o1);
            }
        }
    }
}

// ---------------- causal attention: one block (128 thr) per (b, h, t) ----------------
__global__ void __launch_bounds__(128) attn_kernel(const float* __restrict__ q,
                                                   const float* __restrict__ k,
                                                   const float* __restrict__ v,
                                                   float* __restrict__ out)
{
    __shared__ float qs[HDD];
    __shared__ float p[NT];
    __shared__ float smr[4];
    __shared__ float vpart[128];

    int t  = blockIdx.x;
    int bh = blockIdx.y;
    int b  = bh / NHD, h = bh - b * NHD;
    int tid  = threadIdx.x;
    int lane = tid & 31, warp = tid >> 5;

    const float* qrow = q + (size_t)(b * NT + t) * NC + h * HDD;
    if (tid < HDD) qs[tid] = qrow[tid];
    __syncthreads();

    // QK^T: warp per s-row, coalesced over d
    float lmax = -1e30f;
    for (int s = warp; s <= t; s += 4) {
        const float* krow = k + (size_t)(b * NT + s) * NC + h * HDD;
        float acc = fmaf(qs[lane], krow[lane], qs[lane + 32] * krow[lane + 32]);
        #pragma unroll
        for (int o = 16; o; o >>= 1) acc += __shfl_xor_sync(0xffffffffu, acc, o);
        acc *= ATT_SCALE;
        if (lane == 0) p[s] = acc;
        lmax = fmaxf(lmax, acc);
    }
    if (lane == 0) smr[warp] = lmax;
    __syncthreads();
    lmax = fmaxf(fmaxf(smr[0], smr[1]), fmaxf(smr[2], smr[3]));
    __syncthreads();

    float lsum = 0.f;
    for (int s = tid; s <= t; s += 128) {
        float e = __expf(p[s] - lmax);
        p[s] = e;
        lsum += e;
    }
    float Z = blockSum128(lsum, smr);
    float rZ = 1.0f / Z;

    // V accumulate: 128 threads = 2 s-halves x 64 dims
    int d = tid & 63, half = tid >> 6;
    const float* vcol = v + (size_t)b * NT * NC + h * HDD + d;
    float acc = 0.f;
    for (int s = half; s <= t; s += 2) acc = fmaf(p[s], vcol[(size_t)s * NC], acc);
    vpart[tid] = acc;
    __syncthreads();
    if (tid < HDD)
        out[(size_t)(b * NT + t) * NC + h * HDD + tid] = (vpart[tid] + vpart[tid + 64]) * rZ;
}

// ---------------- launch ----------------
static inline void gemm(const float* A, const float* B, const float* bias,
                        const float* res, float* C, int M, int N, int K,
                        bool relu, bool residual)
{
    dim3 grid(N / 128, M / 128);
    if (relu)          tgemm_kernel<true , false><<<grid, 256>>>(A, B, bias, res, C, M, N, K);
    else if (residual) tgemm_kernel<false, true ><<<grid, 256>>>(A, B, bias, res, C, M, N, K);
    else               tgemm_kernel<false, false><<<grid, 256>>>(A, B, bias, res, C, M, N, K);
}

extern "C" void kernel_launch(void* const* d_in, const int* in_sizes, int n_in,
                              void* d_out, int out_size)
{
    const int*   idx     = (const int*)  d_in[0];
    const float* tok_emb = (const float*)d_in[1];
    const float* pos_emb = (const float*)d_in[2];
    const float* ln1_g   = (const float*)d_in[3];
    const float* ln1_b   = (const float*)d_in[4];
    const float* wq      = (const float*)d_in[5];
    const float* wk      = (const float*)d_in[6];
    const float* wv      = (const float*)d_in[7];
    const float* wo      = (const float*)d_in[8];
    const float* wo_b    = (const float*)d_in[9];
    const float* ln2_g   = (const float*)d_in[10];
    const float* ln2_b   = (const float*)d_in[11];
    const float* w1      = (const float*)d_in[12];
    const float* b1      = (const float*)d_in[13];
    const float* w2      = (const float*)d_in[14];
    const float* b2      = (const float*)d_in[15];
    const float* lnf_g   = (const float*)d_in[16];
    const float* lnf_b   = (const float*)d_in[17];
    const float* lm_w    = (const float*)d_in[18];
    const float* lm_b    = (const float*)d_in[19];
    float* out = (float*)d_out;

    float *x, *h, *q, *k, *v, *att, *ffn;
    cudaGetSymbolAddress((void**)&x,   g_x);
    cudaGetSymbolAddress((void**)&h,   g_h);
    cudaGetSymbolAddress((void**)&q,   g_q);
    cudaGetSymbolAddress((void**)&k,   g_k);
    cudaGetSymbolAddress((void**)&v,   g_v);
    cudaGetSymbolAddress((void**)&att, g_att);
    cudaGetSymbolAddress((void**)&ffn, g_ffn);

    embed_kernel<<<(NM * NC + 255) / 256, 256>>>(idx, tok_emb, pos_emb, x);

    for (int l = 0; l < NL; l++) {
        const float* Wq = wq + (size_t)l * NC * NC;
        const float* Wk = wk + (size_t)l * NC * NC;
        const float* Wv = wv + (size_t)l * NC * NC;
        const float* Wo = wo + (size_t)l * NC * NC;
        const float* W1 = w1 + (size_t)l * NC * NH4;
        const float* W2 = w2 + (size_t)l * NH4 * NC;

        ln_kernel<<<NM, 128>>>(x, ln1_g + l * NC, ln1_b + l * NC, h);
        gemm(h, Wq, nullptr, nullptr, q, NM, NC, NC, false, false);
        gemm(h, Wk, nullptr, nullptr, k, NM, NC, NC, false, false);
        gemm(h, Wv, nullptr, nullptr, v, NM, NC, NC, false, false);

        attn_kernel<<<dim3(NT, NB * NHD), 128>>>(q, k, v, att);

        gemm(att, Wo, wo_b + l * NC, x, x, NM, NC, NC, false, true);

        ln_kernel<<<NM, 128>>>(x, ln2_g + l * NC, ln2_b + l * NC, h);
        gemm(h, W1, b1 + l * NH4, nullptr, ffn, NM, NH4, NC, true, false);
        gemm(ffn, W2, b2 + l * NC, x, x, NM, NC, NH4, false, true);
    }

    ln_kernel<<<NM, 128>>>(x, lnf_g, lnf_b, h);
    gemm(h, lm_w, lm_b, nullptr, out, NM, NVOC, NC, false, false);
}

// round 3
// speedup vs baseline: 3.7116x; 1.1185x over previous
#include <cuda_runtime.h>
#include <cuda_bf16.h>
#include <cstdint>

// ---------------- problem constants ----------------
#define NB   32
#define NT   256
#define NC   384
#define NC3  1152
#define NHD  6
#define HDD  64
#define NL   6
#define NH4  1536
#define NVOC 32000
#define NM   (NB*NT)          // 8192 tokens
#define EPS  1e-5f
#define ATT_SCALE 0.05103103630798288f   // 1/sqrt(384)

// ---------------- scratch ----------------
__device__ float g_x   [NM*NC];
__device__ float g_h   [NM*NC];
__device__ float g_qkv [NM*NC3];
__device__ float g_att [NM*NC];
__device__ float g_ffn [NM*NH4];
__device__ float g_wqkv[NL*NC*NC3];

// ---------------- embedding ----------------
__global__ void embed_kernel(const int* __restrict__ idx,
                             const float* __restrict__ tok,
                             const float* __restrict__ pos,
                             float* __restrict__ x)
{
    int i = blockIdx.x * blockDim.x + threadIdx.x;
    if (i >= NM * NC) return;
    int m = i / NC, c = i - m * NC;
    int t = m & (NT - 1);
    x[i] = tok[idx[m] * NC + c] + pos[t * NC + c];
}

// ---------------- pack W_q|W_k|W_v -> [L][384][1152] ----------------
__global__ void pack_qkv_kernel(const float* __restrict__ wq,
                                const float* __restrict__ wk,
                                const float* __restrict__ wv,
                                float* __restrict__ wqkv)
{
    int i = blockIdx.x * blockDim.x + threadIdx.x;
    if (i >= NL * NC * NC3) return;
    int l = i / (NC * NC3);
    int r = i - l * (NC * NC3);
    int k = r / NC3;
    int n = r - k * NC3;
    const float* src = (n < NC) ? wq : (n < 2 * NC ? wk : wv);
    wqkv[i] = src[(size_t)l * NC * NC + (size_t)k * NC + (n % NC)];
}

// ---------------- reductions ----------------
__device__ __forceinline__ float blockSum128(float v, float* sm)
{
    int lane = threadIdx.x & 31, w = threadIdx.x >> 5;
    #pragma unroll
    for (int o = 16; o; o >>= 1) v += __shfl_xor_sync(0xffffffffu, v, o);
    if (lane == 0) sm[w] = v;
    __syncthreads();
    float r = sm[0] + sm[1] + sm[2] + sm[3];
    __syncthreads();
    return r;
}

// ---------------- layernorm ----------------
__global__ void __launch_bounds__(128) ln_kernel(const float* __restrict__ x,
                                                 const float* __restrict__ g,
                                                 const float* __restrict__ b,
                                                 float* __restrict__ out)
{
    __shared__ float sm[4];
    int row = blockIdx.x;
    const float* xr = x + (size_t)row * NC;
    int tid = threadIdx.x;
    float v0 = xr[tid], v1 = xr[tid + 128], v2 = xr[tid + 256];
    float mean = blockSum128(v0 + v1 + v2, sm) * (1.0f / NC);
    float d0 = v0 - mean, d1 = v1 - mean, d2 = v2 - mean;
    float var = blockSum128(d0 * d0 + d1 * d1 + d2 * d2, sm) * (1.0f / NC);
    float inv = rsqrtf(var + EPS);
    float* orow = out + (size_t)row * NC;
    orow[tid      ] = d0 * inv * g[tid      ] + b[tid      ];
    orow[tid + 128] = d1 * inv * g[tid + 128] + b[tid + 128];
    orow[tid + 256] = d2 * inv * g[tid + 256] + b[tid + 256];
}

// ---------------- TF32 tensor-core GEMM, cp.async 2-stage pipeline ----------------
__device__ __forceinline__ uint32_t f2tf32(float x)
{
    uint32_t u;
    asm("cvt.rna.tf32.f32 %0, %1;" : "=r"(u) : "f"(x));
    return u;
}

#define SA 36    // As row stride (words)
#define SB 132   // Bs row stride (words)
#define ASTAGE (128 * SA)
#define BSTAGE (32 * SB)
#define GEMM_SMEM_BYTES ((2 * ASTAGE + 2 * BSTAGE) * 4)

__device__ __forceinline__ void cp16(float* dst, const float* src)
{
    uint32_t a = (uint32_t)__cvta_generic_to_shared(dst);
    asm volatile("cp.async.cg.shared.global [%0], [%1], 16;" :: "r"(a), "l"(src));
}

template<bool RELU, bool RESIDUAL>
__global__ void __launch_bounds__(256, 2) tgemm_kernel(const float* __restrict__ A,
                                                       const float* __restrict__ B,
                                                       const float* __restrict__ bias,
                                                       const float* __restrict__ res,
                                                       float* __restrict__ C,
                                                       int M, int N, int K)
{
    extern __shared__ float smem[];
    float* As = smem;                 // 2 stages
    float* Bs = smem + 2 * ASTAGE;    // 2 stages

    const int tid    = threadIdx.x;
    const int warpId = tid >> 5;
    const int lane   = tid & 31;
    const int group  = lane >> 2;   // 0..7
    const int tig    = lane & 3;    // 0..3
    const int warpM  = warpId >> 1; // 0..3
    const int warpN  = warpId & 1;  // 0..1

    const int blockM = blockIdx.y * 128;
    const int blockN = blockIdx.x * 128;

    // per-thread copy coordinates (4 x 16B for A, 4 x 16B for B)
    int ar[4], ac[4], br[4], bc[4];
    #pragma unroll
    for (int i = 0; i < 4; i++) {
        int idx = i * 256 + tid;
        ar[i] = idx >> 3;          ac[i] = (idx & 7) * 4;
        br[i] = idx >> 5;          bc[i] = (idx & 31) * 4;
    }

    float c[2][8][4];
    #pragma unroll
    for (int mt = 0; mt < 2; mt++)
        #pragma unroll
        for (int nt = 0; nt < 8; nt++)
            #pragma unroll
            for (int r = 0; r < 4; r++) c[mt][nt][r] = 0.f;

    const int nk = K >> 5;

    auto issue = [&](int kt, int st) {
        #pragma unroll
        for (int i = 0; i < 4; i++) {
            cp16(&As[st * ASTAGE + ar[i] * SA + ac[i]],
                 A + (size_t)(blockM + ar[i]) * K + kt * 32 + ac[i]);
            cp16(&Bs[st * BSTAGE + br[i] * SB + bc[i]],
                 B + (size_t)(kt * 32 + br[i]) * N + blockN + bc[i]);
        }
        asm volatile("cp.async.commit_group;");
    };

    issue(0, 0);

    for (int kt = 0; kt < nk; kt++) {
        const int st = kt & 1;
        if (kt + 1 < nk) {
            issue(kt + 1, (kt + 1) & 1);
            asm volatile("cp.async.wait_group 1;");
        } else {
            asm volatile("cp.async.wait_group 0;");
        }
        __syncthreads();

        const float* Ast = &As[st * ASTAGE];
        const float* Bst = &Bs[st * BSTAGE];
        #pragma unroll
        for (int kk = 0; kk < 4; kk++) {
            const int k = kk * 8;
            uint32_t af[2][4];
            #pragma unroll
            for (int mt = 0; mt < 2; mt++) {
                int mrow = warpM * 32 + mt * 16 + group;
                af[mt][0] = f2tf32(Ast[(mrow    ) * SA + k + tig    ]);
                af[mt][1] = f2tf32(Ast[(mrow + 8) * SA + k + tig    ]);
                af[mt][2] = f2tf32(Ast[(mrow    ) * SA + k + tig + 4]);
                af[mt][3] = f2tf32(Ast[(mrow + 8) * SA + k + tig + 4]);
            }
            uint32_t bf[8][2];
            #pragma unroll
            for (int nt = 0; nt < 8; nt++) {
                int ncol = warpN * 64 + nt * 8 + group;
                bf[nt][0] = f2tf32(Bst[(k + tig    ) * SB + ncol]);
                bf[nt][1] = f2tf32(Bst[(k + tig + 4) * SB + ncol]);
            }
            #pragma unroll
            for (int mt = 0; mt < 2; mt++)
                #pragma unroll
                for (int nt = 0; nt < 8; nt++) {
                    asm volatile(
                        "mma.sync.aligned.m16n8k8.row.col.f32.tf32.tf32.f32 "
                        "{%0,%1,%2,%3}, {%4,%5,%6,%7}, {%8,%9}, {%0,%1,%2,%3};"
                        : "+f"(c[mt][nt][0]), "+f"(c[mt][nt][1]),
                          "+f"(c[mt][nt][2]), "+f"(c[mt][nt][3])
                        : "r"(af[mt][0]), "r"(af[mt][1]), "r"(af[mt][2]), "r"(af[mt][3]),
                          "r"(bf[nt][0]), "r"(bf[nt][1]));
                }
        }
        __syncthreads();
    }

    // epilogue
    #pragma unroll
    for (int mt = 0; mt < 2; mt++) {
        int row0 = blockM + warpM * 32 + mt * 16 + group;
        #pragma unroll
        for (int nt = 0; nt < 8; nt++) {
            int col = blockN + warpN * 64 + nt * 8 + tig * 2;
            float b0 = 0.f, b1 = 0.f;
            if (bias) { b0 = bias[col]; b1 = bias[col + 1]; }
            #pragma unroll
            for (int h = 0; h < 2; h++) {
                int row = row0 + h * 8;
                size_t off = (size_t)row * N + col;
                float o0 = c[mt][nt][h * 2 + 0] + b0;
                float o1 = c[mt][nt][h * 2 + 1] + b1;
                if (RESIDUAL) {
                    float2 r2 = *(const float2*)&res[off];
                    o0 += r2.x; o1 += r2.y;
                }
                if (RELU) { o0 = fmaxf(o0, 0.f); o1 = fmaxf(o1, 0.f); }
                *(float2*)&C[off] = make_float2(o0, o1);
            }
        }
    }
}

// ---------------- causal attention on packed qkv: block per (b,h,t) ----------------
__global__ void __launch_bounds__(128) attn_kernel(const float* __restrict__ qkv,
                                                   float* __restrict__ out)
{
    __shared__ float qs[HDD];
    __shared__ float p[NT];
    __shared__ float smr[4];
    __shared__ float vpart[128];

    int t  = blockIdx.x;
    int bh = blockIdx.y;
    int b  = bh / NHD, h = bh - b * NHD;
    int tid  = threadIdx.x;
    int lane = tid & 31, warp = tid >> 5;

    const float* qrow = qkv + (size_t)(b * NT + t) * NC3 + h * HDD;
    if (tid < HDD) qs[tid] = qrow[tid];
    __syncthreads();

    float lmax = -1e30f;
    for (int s = warp; s <= t; s += 4) {
        const float* krow = qkv + (size_t)(b * NT + s) * NC3 + NC + h * HDD;
        float acc = fmaf(qs[lane], krow[lane], qs[lane + 32] * krow[lane + 32]);
        #pragma unroll
        for (int o = 16; o; o >>= 1) acc += __shfl_xor_sync(0xffffffffu, acc, o);
        acc *= ATT_SCALE;
        if (lane == 0) p[s] = acc;
        lmax = fmaxf(lmax, acc);
    }
    if (lane == 0) smr[warp] = lmax;
    __syncthreads();
    lmax = fmaxf(fmaxf(smr[0], smr[1]), fmaxf(smr[2], smr[3]));
    __syncthreads();

    float lsum = 0.f;
    for (int s = tid; s <= t; s += 128) {
        float e = __expf(p[s] - lmax);
        p[s] = e;
        lsum += e;
    }
    float Z = blockSum128(lsum, smr);
    float rZ = 1.0f / Z;

    int d = tid & 63, half = tid >> 6;
    const float* vcol = qkv + (size_t)(b * NT) * NC3 + 2 * NC + h * HDD + d;
    float acc = 0.f;
    for (int s = half; s <= t; s += 2) acc = fmaf(p[s], vcol[(size_t)s * NC3], acc);
    vpart[tid] = acc;
    __syncthreads();
    if (tid < HDD)
        out[(size_t)(b * NT + t) * NC + h * HDD + tid] = (vpart[tid] + vpart[tid + 64]) * rZ;
}

// ---------------- launch ----------------
static inline void gemm(const float* A, const float* B, const float* bias,
                        const float* res, float* C, int M, int N, int K,
                        bool relu, bool residual)
{
    dim3 grid(N / 128, M / 128);
    if (relu) {
        cudaFuncSetAttribute(tgemm_kernel<true, false>,
                             cudaFuncAttributeMaxDynamicSharedMemorySize, GEMM_SMEM_BYTES);
        tgemm_kernel<true , false><<<grid, 256, GEMM_SMEM_BYTES>>>(A, B, bias, res, C, M, N, K);
    } else if (residual) {
        cudaFuncSetAttribute(tgemm_kernel<false, true>,
                             cudaFuncAttributeMaxDynamicSharedMemorySize, GEMM_SMEM_BYTES);
        tgemm_kernel<false, true ><<<grid, 256, GEMM_SMEM_BYTES>>>(A, B, bias, res, C, M, N, K);
    } else {
        cudaFuncSetAttribute(tgemm_kernel<false, false>,
                             cudaFuncAttributeMaxDynamicSharedMemorySize, GEMM_SMEM_BYTES);
        tgemm_kernel<false, false><<<grid, 256, GEMM_SMEM_BYTES>>>(A, B, bias, res, C, M, N, K);
    }
}

extern "C" void kernel_launch(void* const* d_in, const int* in_sizes, int n_in,
                              void* d_out, int out_size)
{
    const int*   idx     = (const int*)  d_in[0];
    const float* tok_emb = (const float*)d_in[1];
    const float* pos_emb = (const float*)d_in[2];
    const float* ln1_g   = (const float*)d_in[3];
    const float* ln1_b   = (const float*)d_in[4];
    const float* wq      = (const float*)d_in[5];
    const float* wk      = (const float*)d_in[6];
    const float* wv      = (const float*)d_in[7];
    const float* wo      = (const float*)d_in[8];
    const float* wo_b    = (const float*)d_in[9];
    const float* ln2_g   = (const float*)d_in[10];
    const float* ln2_b   = (const float*)d_in[11];
    const float* w1      = (const float*)d_in[12];
    const float* b1      = (const float*)d_in[13];
    const float* w2      = (const float*)d_in[14];
    const float* b2      = (const float*)d_in[15];
    const float* lnf_g   = (const float*)d_in[16];
    const float* lnf_b   = (const float*)d_in[17];
    const float* lm_w    = (const float*)d_in[18];
    const float* lm_b    = (const float*)d_in[19];
    float* out = (float*)d_out;

    float *x, *h, *qkv, *att, *ffn, *wqkv;
    cudaGetSymbolAddress((void**)&x,    g_x);
    cudaGetSymbolAddress((void**)&h,    g_h);
    cudaGetSymbolAddress((void**)&qkv,  g_qkv);
    cudaGetSymbolAddress((void**)&att,  g_att);
    cudaGetSymbolAddress((void**)&ffn,  g_ffn);
    cudaGetSymbolAddress((void**)&wqkv, g_wqkv);

    embed_kernel<<<(NM * NC + 255) / 256, 256>>>(idx, tok_emb, pos_emb, x);
    pack_qkv_kernel<<<(NL * NC * NC3 + 255) / 256, 256>>>(wq, wk, wv, wqkv);

    for (int l = 0; l < NL; l++) {
        const float* Wqkv = wqkv + (size_t)l * NC * NC3;
        const float* Wo   = wo   + (size_t)l * NC * NC;
        const float* W1   = w1   + (size_t)l * NC * NH4;
        const float* W2   = w2   + (size_t)l * NH4 * NC;

        ln_kernel<<<NM, 128>>>(x, ln1_g + l * NC, ln1_b + l * NC, h);
        gemm(h, Wqkv, nullptr, nullptr, qkv, NM, NC3, NC, false, false);

        attn_kernel<<<dim3(NT, NB * NHD), 128>>>(qkv, att);

        gemm(att, Wo, wo_b + l * NC, x, x, NM, NC, NC, false, true);

        ln_kernel<<<NM, 128>>>(x, ln2_g + l * NC, ln2_b + l * NC, h);
        gemm(h, W1, b1 + l * NH4, nullptr, ffn, NM, NH4, NC, true, false);
        gemm(ffn, W2, b2 + l * NC, x, x, NM, NC, NH4, false, true);
    }

    ln_kernel<<<NM, 128>>>(x, lnf_g, lnf_b, h);
    gemm(h, lm_w, lm_b, nullptr, out, NM, NVOC, NC, false, false);
}

// round 4
// speedup vs baseline: 4.8997x; 1.3201x over previous
#include <cuda_runtime.h>
#include <cuda_bf16.h>
#include <cstdint>

// ---------------- problem constants ----------------
#define NB   32
#define NT   256
#define NC   384
#define NC3  1152
#define NHD  6
#define HDD  64
#define NL   6
#define NH4  1536
#define NVOC 32000
#define NM   (NB*NT)          // 8192 tokens
#define EPS  1e-5f
#define ATT_SCALE 0.05103103630798288f   // 1/sqrt(384)

// ---------------- scratch ----------------
__device__ float g_x   [NM*NC];
__device__ float g_h   [NM*NC];
__device__ float g_qkv [NM*NC3];
__device__ float g_att [NM*NC];
__device__ float g_ffn [NM*NH4];
__device__ float g_wqkv[NL*NC*NC3];
__device__ float g_wo  [NL*NC*NC];
__device__ float g_w1  [NL*NC*NH4];
__device__ float g_w2  [NL*NH4*NC];
__device__ float g_lmw [NC*NVOC];

__device__ __forceinline__ uint32_t f2tf32(float x)
{
    uint32_t u;
    asm("cvt.rna.tf32.f32 %0, %1;" : "=r"(u) : "f"(x));
    return u;
}
__device__ __forceinline__ float rtf(float x) { return __uint_as_float(f2tf32(x)); }

// ---------------- embedding ----------------
__global__ void embed_kernel(const int* __restrict__ idx,
                             const float* __restrict__ tok,
                             const float* __restrict__ pos,
                             float* __restrict__ x)
{
    int i = blockIdx.x * blockDim.x + threadIdx.x;
    if (i >= NM * NC) return;
    int m = i / NC, c = i - m * NC;
    int t = m & (NT - 1);
    x[i] = tok[idx[m] * NC + c] + pos[t * NC + c];
}

// ---------------- weight prep (round to tf32) ----------------
__global__ void pack_qkv_kernel(const float* __restrict__ wq,
                                const float* __restrict__ wk,
                                const float* __restrict__ wv,
                                float* __restrict__ wqkv)
{
    int i = blockIdx.x * blockDim.x + threadIdx.x;
    if (i >= NL * NC * NC3) return;
    int l = i / (NC * NC3);
    int r = i - l * (NC * NC3);
    int k = r / NC3;
    int n = r - k * NC3;
    const float* src = (n < NC) ? wq : (n < 2 * NC ? wk : wv);
    wqkv[i] = rtf(src[(size_t)l * NC * NC + (size_t)k * NC + (n % NC)]);
}

__global__ void round_kernel(const float* __restrict__ src, float* __restrict__ dst, int n)
{
    int i = blockIdx.x * blockDim.x + threadIdx.x;
    if (i < n) dst[i] = rtf(src[i]);
}

// ---------------- reductions ----------------
__device__ __forceinline__ float blockSum128(float v, float* sm)
{
    int lane = threadIdx.x & 31, w = threadIdx.x >> 5;
    #pragma unroll
    for (int o = 16; o; o >>= 1) v += __shfl_xor_sync(0xffffffffu, v, o);
    if (lane == 0) sm[w] = v;
    __syncthreads();
    float r = sm[0] + sm[1] + sm[2] + sm[3];
    __syncthreads();
    return r;
}

// ---------------- layernorm (emits tf32-rounded output) ----------------
__global__ void __launch_bounds__(128) ln_kernel(const float* __restrict__ x,
                                                 const float* __restrict__ g,
                                                 const float* __restrict__ b,
                                                 float* __restrict__ out)
{
    __shared__ float sm[4];
    int row = blockIdx.x;
    const float* xr = x + (size_t)row * NC;
    int tid = threadIdx.x;
    float v0 = xr[tid], v1 = xr[tid + 128], v2 = xr[tid + 256];
    float mean = blockSum128(v0 + v1 + v2, sm) * (1.0f / NC);
    float d0 = v0 - mean, d1 = v1 - mean, d2 = v2 - mean;
    float var = blockSum128(d0 * d0 + d1 * d1 + d2 * d2, sm) * (1.0f / NC);
    float inv = rsqrtf(var + EPS);
    float* orow = out + (size_t)row * NC;
    orow[tid      ] = rtf(d0 * inv * g[tid      ] + b[tid      ]);
    orow[tid + 128] = rtf(d1 * inv * g[tid + 128] + b[tid + 128]);
    orow[tid + 256] = rtf(d2 * inv * g[tid + 256] + b[tid + 256]);
}

// ---------------- TF32 tensor-core GEMM, cp.async 2-stage pipeline ----------------
// Inputs already tf32-rounded; inner loop is pure LDS + MMA.
#define SA 36    // As row stride (words)
#define SB 132   // Bs row stride (words)
#define ASTAGE (128 * SA)
#define BSTAGE (32 * SB)
#define GEMM_SMEM_BYTES ((2 * ASTAGE + 2 * BSTAGE) * 4)

__device__ __forceinline__ void cp16(float* dst, const float* src)
{
    uint32_t a = (uint32_t)__cvta_generic_to_shared(dst);
    asm volatile("cp.async.cg.shared.global [%0], [%1], 16;" :: "r"(a), "l"(src));
}

template<bool RELU, bool RESIDUAL, bool ROUND>
__global__ void __launch_bounds__(256, 2) tgemm_kernel(const float* __restrict__ A,
                                                       const float* __restrict__ B,
                                                       const float* __restrict__ bias,
                                                       const float* __restrict__ res,
                                                       float* __restrict__ C,
                                                       int M, int N, int K)
{
    extern __shared__ float smem[];
    float* As = smem;
    float* Bs = smem + 2 * ASTAGE;

    const int tid    = threadIdx.x;
    const int warpId = tid >> 5;
    const int lane   = tid & 31;
    const int group  = lane >> 2;
    const int tig    = lane & 3;
    const int warpM  = warpId >> 1;
    const int warpN  = warpId & 1;

    const int blockM = blockIdx.y * 128;
    const int blockN = blockIdx.x * 128;

    int ar[4], ac[4], br[4], bc[4];
    #pragma unroll
    for (int i = 0; i < 4; i++) {
        int idx = i * 256 + tid;
        ar[i] = idx >> 3;          ac[i] = (idx & 7) * 4;
        br[i] = idx >> 5;          bc[i] = (idx & 31) * 4;
    }

    float c[2][8][4];
    #pragma unroll
    for (int mt = 0; mt < 2; mt++)
        #pragma unroll
        for (int nt = 0; nt < 8; nt++)
            #pragma unroll
            for (int r = 0; r < 4; r++) c[mt][nt][r] = 0.f;

    const int nk = K >> 5;

    auto issue = [&](int kt, int st) {
        #pragma unroll
        for (int i = 0; i < 4; i++) {
            cp16(&As[st * ASTAGE + ar[i] * SA + ac[i]],
                 A + (size_t)(blockM + ar[i]) * K + kt * 32 + ac[i]);
            cp16(&Bs[st * BSTAGE + br[i] * SB + bc[i]],
                 B + (size_t)(kt * 32 + br[i]) * N + blockN + bc[i]);
        }
        asm volatile("cp.async.commit_group;");
    };

    issue(0, 0);

    for (int kt = 0; kt < nk; kt++) {
        const int st = kt & 1;
        if (kt + 1 < nk) {
            issue(kt + 1, (kt + 1) & 1);
            asm volatile("cp.async.wait_group 1;");
        } else {
            asm volatile("cp.async.wait_group 0;");
        }
        __syncthreads();

        const float* Ast = &As[st * ASTAGE];
        const float* Bst = &Bs[st * BSTAGE];
        #pragma unroll
        for (int kk = 0; kk < 4; kk++) {
            const int k = kk * 8;
            uint32_t af[2][4];
            #pragma unroll
            for (int mt = 0; mt < 2; mt++) {
                int mrow = warpM * 32 + mt * 16 + group;
                af[mt][0] = __float_as_uint(Ast[(mrow    ) * SA + k + tig    ]);
                af[mt][1] = __float_as_uint(Ast[(mrow + 8) * SA + k + tig    ]);
                af[mt][2] = __float_as_uint(Ast[(mrow    ) * SA + k + tig + 4]);
                af[mt][3] = __float_as_uint(Ast[(mrow + 8) * SA + k + tig + 4]);
            }
            uint32_t bf[8][2];
            #pragma unroll
            for (int nt = 0; nt < 8; nt++) {
                int ncol = warpN * 64 + nt * 8 + group;
                bf[nt][0] = __float_as_uint(Bst[(k + tig    ) * SB + ncol]);
                bf[nt][1] = __float_as_uint(Bst[(k + tig + 4) * SB + ncol]);
            }
            #pragma unroll
            for (int mt = 0; mt < 2; mt++)
                #pragma unroll
                for (int nt = 0; nt < 8; nt++) {
                    asm volatile(
                        "mma.sync.aligned.m16n8k8.row.col.f32.tf32.tf32.f32 "
                        "{%0,%1,%2,%3}, {%4,%5,%6,%7}, {%8,%9}, {%0,%1,%2,%3};"
                        : "+f"(c[mt][nt][0]), "+f"(c[mt][nt][1]),
                          "+f"(c[mt][nt][2]), "+f"(c[mt][nt][3])
                        : "r"(af[mt][0]), "r"(af[mt][1]), "r"(af[mt][2]), "r"(af[mt][3]),
                          "r"(bf[nt][0]), "r"(bf[nt][1]));
                }
        }
        __syncthreads();
    }

    #pragma unroll
    for (int mt = 0; mt < 2; mt++) {
        int row0 = blockM + warpM * 32 + mt * 16 + group;
        #pragma unroll
        for (int nt = 0; nt < 8; nt++) {
            int col = blockN + warpN * 64 + nt * 8 + tig * 2;
            float b0 = 0.f, b1 = 0.f;
            if (bias) { b0 = bias[col]; b1 = bias[col + 1]; }
            #pragma unroll
            for (int h = 0; h < 2; h++) {
                int row = row0 + h * 8;
                size_t off = (size_t)row * N + col;
                float o0 = c[mt][nt][h * 2 + 0] + b0;
                float o1 = c[mt][nt][h * 2 + 1] + b1;
                if (RESIDUAL) {
                    float2 r2 = *(const float2*)&res[off];
                    o0 += r2.x; o1 += r2.y;
                }
                if (RELU) { o0 = fmaxf(o0, 0.f); o1 = fmaxf(o1, 0.f); }
                if (ROUND) { o0 = rtf(o0); o1 = rtf(o1); }
                *(float2*)&C[off] = make_float2(o0, o1);
            }
        }
    }
}

// ---------------- flash attention: thread-per-query, K/V chunks in smem ----------------
// grid (2, NB*NHD); block 128 threads = 128 queries of one (b,h)
__global__ void __launch_bounds__(128, 3) attn_kernel(const float* __restrict__ qkv,
                                                      float* __restrict__ att)
{
    __shared__ float ks[64 * 64];
    __shared__ float vs[64 * 64];

    int qt  = blockIdx.x;
    int bh  = blockIdx.y;
    int b   = bh / NHD, h = bh - b * NHD;
    int tid = threadIdx.x;
    int t   = qt * 128 + tid;

    float4 q4[16];
    {
        const float4* qrow = (const float4*)(qkv + (size_t)(b * NT + t) * NC3 + h * HDD);
        #pragma unroll
        for (int i = 0; i < 16; i++) q4[i] = qrow[i];
    }
    float4 o4[16];
    #pragma unroll
    for (int i = 0; i < 16; i++) o4[i] = make_float4(0.f, 0.f, 0.f, 0.f);
    float m = -1e30f, l = 0.f;

    const int nch = (qt + 1) * 2;
    for (int ch = 0; ch < nch; ch++) {
        const int s0 = ch * 64;
        #pragma unroll
        for (int i = 0; i < 8; i++) {
            int idx = i * 128 + tid;           // float4 units, 1024 total
            int r = idx >> 4, c4 = (idx & 15) * 4;
            const float* kr = qkv + (size_t)(b * NT + s0 + r) * NC3 + NC     + h * HDD + c4;
            const float* vr = qkv + (size_t)(b * NT + s0 + r) * NC3 + 2 * NC + h * HDD + c4;
            *(float4*)&ks[r * 64 + c4] = *(const float4*)kr;
            *(float4*)&vs[r * 64 + c4] = *(const float4*)vr;
        }
        __syncthreads();

        if (t >= s0) {
            int smax = min(63, t - s0);
            for (int g = 0; g <= smax; g += 8) {
                int cnt = min(8, smax - g + 1);
                float sc[8];
                #pragma unroll
                for (int j = 0; j < 8; j++) {
                    if (j < cnt) {
                        const float4* kr = (const float4*)&ks[(g + j) * 64];
                        float acc = 0.f;
                        #pragma unroll
                        for (int i = 0; i < 16; i++) {
                            float4 kv = kr[i];
                            acc = fmaf(q4[i].x, kv.x, acc);
                            acc = fmaf(q4[i].y, kv.y, acc);
                            acc = fmaf(q4[i].z, kv.z, acc);
                            acc = fmaf(q4[i].w, kv.w, acc);
                        }
                        sc[j] = acc * ATT_SCALE;
                    } else sc[j] = -1e30f;
                }
                float mloc = sc[0];
                #pragma unroll
                for (int j = 1; j < 8; j++) mloc = fmaxf(mloc, sc[j]);
                float mnew = fmaxf(m, mloc);
                float alpha = __expf(m - mnew);
                m = mnew;
                l *= alpha;
                #pragma unroll
                for (int i = 0; i < 16; i++) {
                    o4[i].x *= alpha; o4[i].y *= alpha;
                    o4[i].z *= alpha; o4[i].w *= alpha;
                }
                #pragma unroll
                for (int j = 0; j < 8; j++) {
                    if (j < cnt) {
                        float p = __expf(sc[j] - m);
                        l += p;
                        const float4* vr = (const float4*)&vs[(g + j) * 64];
                        #pragma unroll
                        for (int i = 0; i < 16; i++) {
                            float4 vv = vr[i];
                            o4[i].x = fmaf(p, vv.x, o4[i].x);
                            o4[i].y = fmaf(p, vv.y, o4[i].y);
                            o4[i].z = fmaf(p, vv.z, o4[i].z);
                            o4[i].w = fmaf(p, vv.w, o4[i].w);
                        }
                    }
                }
            }
        }
        __syncthreads();
    }

    float rl = 1.0f / l;
    float4* orow = (float4*)(att + (size_t)(b * NT + t) * NC + h * HDD);
    #pragma unroll
    for (int i = 0; i < 16; i++) {
        float4 o = o4[i];
        o.x = rtf(o.x * rl); o.y = rtf(o.y * rl);
        o.z = rtf(o.z * rl); o.w = rtf(o.w * rl);
        orow[i] = o;
    }
}

// ---------------- launch helpers ----------------
template<bool RELU, bool RESIDUAL, bool ROUND>
static inline void gemm_t(const float* A, const float* B, const float* bias,
                          const float* res, float* C, int M, int N, int K)
{
    dim3 grid(N / 128, M / 128);
    cudaFuncSetAttribute(tgemm_kernel<RELU, RESIDUAL, ROUND>,
                         cudaFuncAttributeMaxDynamicSharedMemorySize, GEMM_SMEM_BYTES);
    tgemm_kernel<RELU, RESIDUAL, ROUND><<<grid, 256, GEMM_SMEM_BYTES>>>(A, B, bias, res, C, M, N, K);
}

extern "C" void kernel_launch(void* const* d_in, const int* in_sizes, int n_in,
                              void* d_out, int out_size)
{
    const int*   idx     = (const int*)  d_in[0];
    const float* tok_emb = (const float*)d_in[1];
    const float* pos_emb = (const float*)d_in[2];
    const float* ln1_g   = (const float*)d_in[3];
    const float* ln1_b   = (const float*)d_in[4];
    const float* wq      = (const float*)d_in[5];
    const float* wk      = (const float*)d_in[6];
    const float* wv      = (const float*)d_in[7];
    const float* wo      = (const float*)d_in[8];
    const float* wo_b    = (const float*)d_in[9];
    const float* ln2_g   = (const float*)d_in[10];
    const float* ln2_b   = (const float*)d_in[11];
    const float* w1      = (const float*)d_in[12];
    const float* b1      = (const float*)d_in[13];
    const float* w2      = (const float*)d_in[14];
    const float* b2      = (const float*)d_in[15];
    const float* lnf_g   = (const float*)d_in[16];
    const float* lnf_b   = (const float*)d_in[17];
    const float* lm_w    = (const float*)d_in[18];
    const float* lm_b    = (const float*)d_in[19];
    float* out = (float*)d_out;

    float *x, *h, *qkv, *att, *ffn, *wqkv, *wor, *w1r, *w2r, *lmwr;
    cudaGetSymbolAddress((void**)&x,    g_x);
    cudaGetSymbolAddress((void**)&h,    g_h);
    cudaGetSymbolAddress((void**)&qkv,  g_qkv);
    cudaGetSymbolAddress((void**)&att,  g_att);
    cudaGetSymbolAddress((void**)&ffn,  g_ffn);
    cudaGetSymbolAddress((void**)&wqkv, g_wqkv);
    cudaGetSymbolAddress((void**)&wor,  g_wo);
    cudaGetSymbolAddress((void**)&w1r,  g_w1);
    cudaGetSymbolAddress((void**)&w2r,  g_w2);
    cudaGetSymbolAddress((void**)&lmwr, g_lmw);

    embed_kernel<<<(NM * NC + 255) / 256, 256>>>(idx, tok_emb, pos_emb, x);
    pack_qkv_kernel<<<(NL * NC * NC3 + 255) / 256, 256>>>(wq, wk, wv, wqkv);
    round_kernel<<<(NL * NC * NC  + 255) / 256, 256>>>(wo,   wor,  NL * NC * NC);
    round_kernel<<<(NL * NC * NH4 + 255) / 256, 256>>>(w1,   w1r,  NL * NC * NH4);
    round_kernel<<<(NL * NH4 * NC + 255) / 256, 256>>>(w2,   w2r,  NL * NH4 * NC);
    round_kernel<<<(NC * NVOC     + 255) / 256, 256>>>(lm_w, lmwr, NC * NVOC);

    for (int l = 0; l < NL; l++) {
        const float* Wqkv = wqkv + (size_t)l * NC * NC3;
        const float* Wo   = wor  + (size_t)l * NC * NC;
        const float* W1   = w1r  + (size_t)l * NC * NH4;
        const float* W2   = w2r  + (size_t)l * NH4 * NC;

        ln_kernel<<<NM, 128>>>(x, ln1_g + l * NC, ln1_b + l * NC, h);
        gemm_t<false, false, false>(h, Wqkv, nullptr, nullptr, qkv, NM, NC3, NC);

        attn_kernel<<<dim3(2, NB * NHD), 128>>>(qkv, att);

        gemm_t<false, true, false>(att, Wo, wo_b + l * NC, x, x, NM, NC, NC);

        ln_kernel<<<NM, 128>>>(x, ln2_g + l * NC, ln2_b + l * NC, h);
        gemm_t<true, false, true>(h, W1, b1 + l * NH4, nullptr, ffn, NM, NH4, NC);
        gemm_t<false, true, false>(ffn, W2, b2 + l * NC, x, x, NM, NC, NH4);
    }

    ln_kernel<<<NM, 128>>>(x, lnf_g, lnf_b, h);
    gemm_t<false, false, false>(h, lmwr, lm_b, nullptr, out, NM, NVOC, NC);
}

// round 6
// speedup vs baseline: 4.9950x; 1.0195x over previous
#include <cuda_runtime.h>
#include <cuda_bf16.h>
#include <cstdint>

// ---------------- problem constants ----------------
#define NB   32
#define NT   256
#define NC   384
#define NC3  1152
#define NHD  6
#define HDD  64
#define NL   6
#define NH4  1536
#define NVOC 32000
#define NM   (NB*NT)          // 8192 tokens
#define EPS  1e-5f
#define ATT_SCALE 0.05103103630798288f   // 1/sqrt(384)

// ---------------- scratch ----------------
__device__ float g_x   [NM*NC];
__device__ float g_h   [NM*NC];
__device__ float g_qkv [NM*NC3];
__device__ float g_att [NM*NC];
__device__ float g_ffn [NM*NH4];
__device__ float g_wqkv[NL*NC*NC3];
__device__ float g_wo  [NL*NC*NC];
__device__ float g_w1  [NL*NC*NH4];
__device__ float g_w2  [NL*NH4*NC];
__device__ float g_lmw [NC*NVOC];

__device__ __forceinline__ uint32_t f2tf32(float x)
{
    uint32_t u;
    asm("cvt.rna.tf32.f32 %0, %1;" : "=r"(u) : "f"(x));
    return u;
}
__device__ __forceinline__ float rtf(float x) { return __uint_as_float(f2tf32(x)); }

// ---------------- embedding ----------------
__global__ void embed_kernel(const int* __restrict__ idx,
                             const float* __restrict__ tok,
                             const float* __restrict__ pos,
                             float* __restrict__ x)
{
    int i = blockIdx.x * blockDim.x + threadIdx.x;
    if (i >= NM * NC) return;
    int m = i / NC, c = i - m * NC;
    int t = m & (NT - 1);
    x[i] = tok[idx[m] * NC + c] + pos[t * NC + c];
}

// ---------------- weight prep (round to tf32) ----------------
__global__ void pack_qkv_kernel(const float* __restrict__ wq,
                                const float* __restrict__ wk,
                                const float* __restrict__ wv,
                                float* __restrict__ wqkv)
{
    int i = blockIdx.x * blockDim.x + threadIdx.x;
    if (i >= NL * NC * NC3) return;
    int l = i / (NC * NC3);
    int r = i - l * (NC * NC3);
    int k = r / NC3;
    int n = r - k * NC3;
    const float* src = (n < NC) ? wq : (n < 2 * NC ? wk : wv);
    wqkv[i] = rtf(src[(size_t)l * NC * NC + (size_t)k * NC + (n % NC)]);
}

__global__ void round_kernel(const float* __restrict__ src, float* __restrict__ dst, int n)
{
    int i = blockIdx.x * blockDim.x + threadIdx.x;
    if (i < n) dst[i] = rtf(src[i]);
}

// ---------------- layernorm: warp per row, float4, shfl-only ----------------
__global__ void __launch_bounds__(256) ln_kernel(const float* __restrict__ x,
                                                 const float* __restrict__ g,
                                                 const float* __restrict__ b,
                                                 float* __restrict__ out)
{
    int warp = threadIdx.x >> 5, lane = threadIdx.x & 31;
    int row  = blockIdx.x * 8 + warp;
    const float4* xr = (const float4*)(x + (size_t)row * NC);

    float4 v[3];
    #pragma unroll
    for (int i = 0; i < 3; i++) v[i] = xr[i * 32 + lane];

    float s = 0.f;
    #pragma unroll
    for (int i = 0; i < 3; i++) s += v[i].x + v[i].y + v[i].z + v[i].w;
    #pragma unroll
    for (int o = 16; o; o >>= 1) s += __shfl_xor_sync(0xffffffffu, s, o);
    float mean = s * (1.0f / NC);

    float q = 0.f;
    #pragma unroll
    for (int i = 0; i < 3; i++) {
        float dx = v[i].x - mean, dy = v[i].y - mean, dz = v[i].z - mean, dw = v[i].w - mean;
        q += dx * dx + dy * dy + dz * dz + dw * dw;
        v[i] = make_float4(dx, dy, dz, dw);
    }
    #pragma unroll
    for (int o = 16; o; o >>= 1) q += __shfl_xor_sync(0xffffffffu, q, o);
    float inv = rsqrtf(q * (1.0f / NC) + EPS);

    const float4* g4 = (const float4*)g;
    const float4* b4 = (const float4*)b;
    float4* o4 = (float4*)(out + (size_t)row * NC);
    #pragma unroll
    for (int i = 0; i < 3; i++) {
        float4 gg = g4[i * 32 + lane], bb = b4[i * 32 + lane];
        float4 o;
        o.x = rtf(v[i].x * inv * gg.x + bb.x);
        o.y = rtf(v[i].y * inv * gg.y + bb.y);
        o.z = rtf(v[i].z * inv * gg.z + bb.z);
        o.w = rtf(v[i].w * inv * gg.w + bb.w);
        o4[i * 32 + lane] = o;
    }
}

// ---------------- TF32 tensor-core GEMM, 3-stage cp.async pipeline ----------------
#define SA 36    // As row stride (words)
#define SB 132   // Bs row stride (words)
#define ASTAGE (128 * SA)
#define BSTAGE (32 * SB)
#define NSTAGE 3
#define GEMM_SMEM_BYTES (NSTAGE * (ASTAGE + BSTAGE) * 4)

__device__ __forceinline__ void cp16(float* dst, const float* src)
{
    uint32_t a = (uint32_t)__cvta_generic_to_shared(dst);
    asm volatile("cp.async.cg.shared.global [%0], [%1], 16;" :: "r"(a), "l"(src));
}

template<bool RELU, bool RESIDUAL, bool ROUND>
__global__ void __launch_bounds__(256, 2) tgemm_kernel(const float* __restrict__ A,
                                                       const float* __restrict__ B,
                                                       const float* __restrict__ bias,
                                                       const float* __restrict__ res,
                                                       float* __restrict__ C,
                                                       int M, int N, int K)
{
    extern __shared__ float smem[];
    float* As = smem;
    float* Bs = smem + NSTAGE * ASTAGE;

    const int tid    = threadIdx.x;
    const int warpId = tid >> 5;
    const int lane   = tid & 31;
    const int group  = lane >> 2;
    const int tig    = lane & 3;
    const int warpM  = warpId >> 1;
    const int warpN  = warpId & 1;

    const int blockM = blockIdx.y * 128;
    const int blockN = blockIdx.x * 128;

    int ar[4], ac[4], br[4], bc[4];
    #pragma unroll
    for (int i = 0; i < 4; i++) {
        int idx = i * 256 + tid;
        ar[i] = idx >> 3;          ac[i] = (idx & 7) * 4;
        br[i] = idx >> 5;          bc[i] = (idx & 31) * 4;
    }

    float c[2][8][4];
    #pragma unroll
    for (int mt = 0; mt < 2; mt++)
        #pragma unroll
        for (int nt = 0; nt < 8; nt++)
            #pragma unroll
            for (int r = 0; r < 4; r++) c[mt][nt][r] = 0.f;

    const int nk = K >> 5;

    auto issue = [&](int kt) {
        const int st = kt % NSTAGE;
        #pragma unroll
        for (int i = 0; i < 4; i++) {
            cp16(&As[st * ASTAGE + ar[i] * SA + ac[i]],
                 A + (size_t)(blockM + ar[i]) * K + kt * 32 + ac[i]);
            cp16(&Bs[st * BSTAGE + br[i] * SB + bc[i]],
                 B + (size_t)(kt * 32 + br[i]) * N + blockN + bc[i]);
        }
        asm volatile("cp.async.commit_group;");
    };

    issue(0);
    issue(1);

    for (int kt = 0; kt < nk; kt++) {
        if (kt + 1 < nk) asm volatile("cp.async.wait_group 1;");
        else             asm volatile("cp.async.wait_group 0;");
        __syncthreads();

        if (kt + 2 < nk) issue(kt + 2);

        const int st = kt % NSTAGE;
        const float* Ast = &As[st * ASTAGE];
        const float* Bst = &Bs[st * BSTAGE];
        #pragma unroll
        for (int kk = 0; kk < 4; kk++) {
            const int k = kk * 8;
            uint32_t af[2][4];
            #pragma unroll
            for (int mt = 0; mt < 2; mt++) {
                int mrow = warpM * 32 + mt * 16 + group;
                af[mt][0] = __float_as_uint(Ast[(mrow    ) * SA + k + tig    ]);
                af[mt][1] = __float_as_uint(Ast[(mrow + 8) * SA + k + tig    ]);
                af[mt][2] = __float_as_uint(Ast[(mrow    ) * SA + k + tig + 4]);
                af[mt][3] = __float_as_uint(Ast[(mrow + 8) * SA + k + tig + 4]);
            }
            uint32_t bf[8][2];
            #pragma unroll
            for (int nt = 0; nt < 8; nt++) {
                int ncol = warpN * 64 + nt * 8 + group;
                bf[nt][0] = __float_as_uint(Bst[(k + tig    ) * SB + ncol]);
                bf[nt][1] = __float_as_uint(Bst[(k + tig + 4) * SB + ncol]);
            }
            #pragma unroll
            for (int mt = 0; mt < 2; mt++)
                #pragma unroll
                for (int nt = 0; nt < 8; nt++) {
                    asm volatile(
                        "mma.sync.aligned.m16n8k8.row.col.f32.tf32.tf32.f32 "
                        "{%0,%1,%2,%3}, {%4,%5,%6,%7}, {%8,%9}, {%0,%1,%2,%3};"
                        : "+f"(c[mt][nt][0]), "+f"(c[mt][nt][1]),
                          "+f"(c[mt][nt][2]), "+f"(c[mt][nt][3])
                        : "r"(af[mt][0]), "r"(af[mt][1]), "r"(af[mt][2]), "r"(af[mt][3]),
                          "r"(bf[nt][0]), "r"(bf[nt][1]));
                }
        }
    }

    #pragma unroll
    for (int mt = 0; mt < 2; mt++) {
        int row0 = blockM + warpM * 32 + mt * 16 + group;
        #pragma unroll
        for (int nt = 0; nt < 8; nt++) {
            int col = blockN + warpN * 64 + nt * 8 + tig * 2;
            float b0 = 0.f, b1 = 0.f;
            if (bias) { b0 = bias[col]; b1 = bias[col + 1]; }
            #pragma unroll
            for (int h = 0; h < 2; h++) {
                int row = row0 + h * 8;
                size_t off = (size_t)row * N + col;
                float o0 = c[mt][nt][h * 2 + 0] + b0;
                float o1 = c[mt][nt][h * 2 + 1] + b1;
                if (RESIDUAL) {
                    float2 r2 = *(const float2*)&res[off];
                    o0 += r2.x; o1 += r2.y;
                }
                if (RELU) { o0 = fmaxf(o0, 0.f); o1 = fmaxf(o1, 0.f); }
                if (ROUND) { o0 = rtf(o0); o1 = rtf(o1); }
                *(float2*)&C[off] = make_float2(o0, o1);
            }
        }
    }
}

// ---------------- flash attention: thread-per-query, K/V chunks in smem ----------------
__global__ void __launch_bounds__(128, 3) attn_kernel(const float* __restrict__ qkv,
                                                      float* __restrict__ att)
{
    __shared__ float ks[64 * 64];
    __shared__ float vs[64 * 64];

    int qt  = blockIdx.x;
    int bh  = blockIdx.y;
    int b   = bh / NHD, h = bh - b * NHD;
    int tid = threadIdx.x;
    int t   = qt * 128 + tid;

    float4 q4[16];
    {
        const float4* qrow = (const float4*)(qkv + (size_t)(b * NT + t) * NC3 + h * HDD);
        #pragma unroll
        for (int i = 0; i < 16; i++) q4[i] = qrow[i];
    }
    float4 o4[16];
    #pragma unroll
    for (int i = 0; i < 16; i++) o4[i] = make_float4(0.f, 0.f, 0.f, 0.f);
    float m = -1e30f, l = 0.f;

    const int nch = (qt + 1) * 2;
    for (int ch = 0; ch < nch; ch++) {
        const int s0 = ch * 64;
        #pragma unroll
        for (int i = 0; i < 8; i++) {
            int idx = i * 128 + tid;
            int r = idx >> 4, c4 = (idx & 15) * 4;
            const float* kr = qkv + (size_t)(b * NT + s0 + r) * NC3 + NC     + h * HDD + c4;
            const float* vr = qkv + (size_t)(b * NT + s0 + r) * NC3 + 2 * NC + h * HDD + c4;
            *(float4*)&ks[r * 64 + c4] = *(const float4*)kr;
            *(float4*)&vs[r * 64 + c4] = *(const float4*)vr;
        }
        __syncthreads();

        if (t >= s0) {
            int smax = min(63, t - s0);
            for (int g = 0; g <= smax; g += 8) {
                int cnt = min(8, smax - g + 1);
                float sc[8];
                #pragma unroll
                for (int j = 0; j < 8; j++) {
                    if (j < cnt) {
                        const float4* kr = (const float4*)&ks[(g + j) * 64];
                        float acc = 0.f;
                        #pragma unroll
                        for (int i = 0; i < 16; i++) {
                            float4 kv = kr[i];
                            acc = fmaf(q4[i].x, kv.x, acc);
                            acc = fmaf(q4[i].y, kv.y, acc);
                            acc = fmaf(q4[i].z, kv.z, acc);
                            acc = fmaf(q4[i].w, kv.w, acc);
                        }
                        sc[j] = acc * ATT_SCALE;
                    } else sc[j] = -1e30f;
                }
                float mloc = sc[0];
                #pragma unroll
                for (int j = 1; j < 8; j++) mloc = fmaxf(mloc, sc[j]);
                float mnew = fmaxf(m, mloc);
                float alpha = __expf(m - mnew);
                m = mnew;
                l *= alpha;
                #pragma unroll
                for (int i = 0; i < 16; i++) {
                    o4[i].x *= alpha; o4[i].y *= alpha;
                    o4[i].z *= alpha; o4[i].w *= alpha;
                }
                #pragma unroll
                for (int j = 0; j < 8; j++) {
                    if (j < cnt) {
                        float p = __expf(sc[j] - m);
                        l += p;
                        const float4* vr = (const float4*)&vs[(g + j) * 64];
                        #pragma unroll
                        for (int i = 0; i < 16; i++) {
                            float4 vv = vr[i];
                            o4[i].x = fmaf(p, vv.x, o4[i].x);
                            o4[i].y = fmaf(p, vv.y, o4[i].y);
                            o4[i].z = fmaf(p, vv.z, o4[i].z);
                            o4[i].w = fmaf(p, vv.w, o4[i].w);
                        }
                    }
                }
            }
        }
        __syncthreads();
    }

    float rl = 1.0f / l;
    float4* orow = (float4*)(att + (size_t)(b * NT + t) * NC + h * HDD);
    #pragma unroll
    for (int i = 0; i < 16; i++) {
        float4 o = o4[i];
        o.x = rtf(o.x * rl); o.y = rtf(o.y * rl);
        o.z = rtf(o.z * rl); o.w = rtf(o.w * rl);
        orow[i] = o;
    }
}

// ---------------- launch helpers ----------------
template<bool RELU, bool RESIDUAL, bool ROUND>
static inline void gemm_t(const float* A, const float* B, const float* bias,
                          const float* res, float* C, int M, int N, int K)
{
    dim3 grid(N / 128, M / 128);
    cudaFuncSetAttribute(tgemm_kernel<RELU, RESIDUAL, ROUND>,
                         cudaFuncAttributeMaxDynamicSharedMemorySize, GEMM_SMEM_BYTES);
    tgemm_kernel<RELU, RESIDUAL, ROUND><<<grid, 256, GEMM_SMEM_BYTES>>>(A, B, bias, res, C, M, N, K);
}

extern "C" void kernel_launch(void* const* d_in, const int* in_sizes, int n_in,
                              void* d_out, int out_size)
{
    const int*   idx     = (const int*)  d_in[0];
    const float* tok_emb = (const float*)d_in[1];
    const float* pos_emb = (const float*)d_in[2];
    const float* ln1_g   = (const float*)d_in[3];
    const float* ln1_b   = (const float*)d_in[4];
    const float* wq      = (const float*)d_in[5];
    const float* wk      = (const float*)d_in[6];
    const float* wv      = (const float*)d_in[7];
    const float* wo      = (const float*)d_in[8];
    const float* wo_b    = (const float*)d_in[9];
    const float* ln2_g   = (const float*)d_in[10];
    const float* ln2_b   = (const float*)d_in[11];
    const float* w1      = (const float*)d_in[12];
    const float* b1      = (const float*)d_in[13];
    const float* w2      = (const float*)d_in[14];
    const float* b2      = (const float*)d_in[15];
    const float* lnf_g   = (const float*)d_in[16];
    const float* lnf_b   = (const float*)d_in[17];
    const float* lm_w    = (const float*)d_in[18];
    const float* lm_b    = (const float*)d_in[19];
    float* out = (float*)d_out;

    float *x, *h, *qkv, *att, *ffn, *wqkv, *wor, *w1r, *w2r, *lmwr;
    cudaGetSymbolAddress((void**)&x,    g_x);
    cudaGetSymbolAddress((void**)&h,    g_h);
    cudaGetSymbolAddress((void**)&qkv,  g_qkv);
    cudaGetSymbolAddress((void**)&att,  g_att);
    cudaGetSymbolAddress((void**)&ffn,  g_ffn);
    cudaGetSymbolAddress((void**)&wqkv, g_wqkv);
    cudaGetSymbolAddress((void**)&wor,  g_wo);
    cudaGetSymbolAddress((void**)&w1r,  g_w1);
    cudaGetSymbolAddress((void**)&w2r,  g_w2);
    cudaGetSymbolAddress((void**)&lmwr, g_lmw);

    embed_kernel<<<(NM * NC + 255) / 256, 256>>>(idx, tok_emb, pos_emb, x);
    pack_qkv_kernel<<<(NL * NC * NC3 + 255) / 256, 256>>>(wq, wk, wv, wqkv);
    round_kernel<<<(NL * NC * NC  + 255) / 256, 256>>>(wo,   wor,  NL * NC * NC);
    round_kernel<<<(NL * NC * NH4 + 255) / 256, 256>>>(w1,   w1r,  NL * NC * NH4);
    round_kernel<<<(NL * NH4 * NC + 255) / 256, 256>>>(w2,   w2r,  NL * NH4 * NC);
    round_kernel<<<(NC * NVOC     + 255) / 256, 256>>>(lm_w, lmwr, NC * NVOC);

    for (int l = 0; l < NL; l++) {
        const float* Wqkv = wqkv + (size_t)l * NC * NC3;
        const float* Wo   = wor  + (size_t)l * NC * NC;
        const float* W1   = w1r  + (size_t)l * NC * NH4;
        const float* W2   = w2r  + (size_t)l * NH4 * NC;

        ln_kernel<<<NM / 8, 256>>>(x, ln1_g + l * NC, ln1_b + l * NC, h);
        gemm_t<false, false, false>(h, Wqkv, nullptr, nullptr, qkv, NM, NC3, NC);

        attn_kernel<<<dim3(2, NB * NHD), 128>>>(qkv, att);

        gemm_t<false, true, false>(att, Wo, wo_b + l * NC, x, x, NM, NC, NC);

        ln_kernel<<<NM / 8, 256>>>(x, ln2_g + l * NC, ln2_b + l * NC, h);
        gemm_t<true, false, true>(h, W1, b1 + l * NH4, nullptr, ffn, NM, NH4, NC);
        gemm_t<false, true, false>(ffn, W2, b2 + l * NC, x, x, NM, NC, NH4);
    }

    ln_kernel<<<NM / 8, 256>>>(x, lnf_g, lnf_b, h);
    gemm_t<false, false, false>(h, lmwr, lm_b, nullptr, out, NM, NVOC, NC);
}